// round 3
// baseline (speedup 1.0000x reference)
#include <cuda_runtime.h>
#include <cuda_bf16.h>

// KOrderGPMap: B=32, L=64, C=4. x is one-hot => all einsums are gathers.
// phi[b] = th0 + sum_l th1[s_l] + sum_{l0<l1} th2[s0*256+s1]
//        + sum_{l0<l1<l2} th3[s0*65536+s1*256+s2],  s_l = 4*l + idx[b,l].

#define B 32
#define L 64
#define NTHREADS 128   // 4 warps

__global__ void zero_out_kernel(float* __restrict__ out) {
    if (threadIdx.x < B) out[threadIdx.x] = 0.0f;
}

__global__ __launch_bounds__(NTHREADS)
void kgp_kernel(const float* __restrict__ x,      // (B, 256)
                const float* __restrict__ th0,    // (1,)
                const float* __restrict__ th1,    // (256,)
                const float* __restrict__ th2,    // (256*256,)
                const float* __restrict__ th3,    // (256^3,)
                float* __restrict__ out)          // (B,)
{
    const int l0  = blockIdx.x;   // 0..63
    const int b   = blockIdx.y;   // 0..31
    const int tid = threadIdx.x;
    const int warp = tid >> 5;
    const int lane = tid & 31;

    __shared__ int s[L];
    __shared__ float wsum[NTHREADS / 32];

    // Decode one-hot: c = 0*x0 + 1*x1 + 2*x2 + 3*x3 (exact for one-hot).
    if (tid < L) {
        const float4 v = reinterpret_cast<const float4*>(x)[b * L + tid];
        int c = (int)(v.y + 2.0f * v.z + 3.0f * v.w + 0.5f);
        s[tid] = tid * 4 + c;
    }
    __syncthreads();

    float acc = 0.0f;

    const int s0 = s[l0];
    const int base0 = s0 << 16;   // s0 * 65536

    // Pairs (l1, l2) with l0 < l1 < l2. Warps stride over l1, lanes over l2.
    for (int l1 = l0 + 1 + warp; l1 < L; l1 += (NTHREADS / 32)) {
        const int s1 = s[l1];
        const int base = base0 + (s1 << 8);
        float a = 0.0f;
        #pragma unroll 2
        for (int l2 = l1 + 1 + lane; l2 < L; l2 += 32) {
            a += __ldg(&th3[base + s[l2]]);
        }
        acc += a;
        // order-2 term for this (l0, l1) pair, counted once.
        if (lane == 0) acc += __ldg(&th2[(s0 << 8) + s1]);
    }

    // order-1 + theta_0: handled once per batch by block l0==0, warp 0.
    if (l0 == 0 && warp == 0) {
        acc += __ldg(&th1[s[lane]]) + __ldg(&th1[s[lane + 32]]);
        if (lane == 0) acc += th0[0];
    }

    // Warp reduce.
    #pragma unroll
    for (int off = 16; off > 0; off >>= 1)
        acc += __shfl_xor_sync(0xffffffffu, acc, off);
    if (lane == 0) wsum[warp] = acc;
    __syncthreads();

    if (tid == 0) {
        float total = wsum[0] + wsum[1] + wsum[2] + wsum[3];
        atomicAdd(&out[b], total);
    }
}

extern "C" void kernel_launch(void* const* d_in, const int* in_sizes, int n_in,
                              void* d_out, int out_size) {
    const float* x   = (const float*)d_in[0];
    const float* th0 = (const float*)d_in[1];
    const float* th1 = (const float*)d_in[2];
    const float* th2 = (const float*)d_in[3];
    const float* th3 = (const float*)d_in[4];
    float* out = (float*)d_out;

    zero_out_kernel<<<1, 32>>>(out);
    dim3 grid(L, B);
    kgp_kernel<<<grid, NTHREADS>>>(x, th0, th1, th2, th3, out);
}